// round 11
// baseline (speedup 1.0000x reference)
#include <cuda_runtime.h>
#include <math.h>

#define SS 7
#define NB 49          // boxes per image
#define NC 20          // classes
#define NBATCH 4096
#define DD 30          // channels per cell

#define AP_GRID 784    // 784 * 256 = 200704 = NBATCH*NB exactly

// ---------------- scratch (device globals; no allocation) ----------------
__device__ __align__(256) int    g_records[NBATCH * NB];   // packed per-pred record
__device__ __align__(256) int    g_nvalid[NC * NBATCH];    // per class, per image valid count
__device__ __align__(256) int    g_ntp[NC * NBATCH];       // per class, per image tp count
__device__ __align__(256) int    g_ngt[NC * NBATCH];       // per class, per image GT count
__device__ __align__(256) int    g_offv[NC * NBATCH];      // exclusive scans over images
__device__ __align__(256) int    g_offt[NC * NBATCH];
__device__ int    g_gt[NC];                                // per-class GT totals (from k_scan)
__device__ double g_ap[NC];                                // per-class AP accumulators
__device__ int    g_done;                                  // k_ap completion ticket (0 at start; reset by last block)

// ---------------- helpers ----------------
__device__ __forceinline__ float sigm(float x) { return 1.0f / (1.0f + expf(-x)); }

__device__ __forceinline__ float iou_v(float ax0, float ay0, float ax1, float ay1, float aar,
                                       float4 b, float bar) {
    float lx = fmaxf(ax0, b.x), ly = fmaxf(ay0, b.y);
    float rx = fminf(ax1, b.z), ry = fminf(ay1, b.w);
    float w = fmaxf(rx - lx, 0.0f), h = fmaxf(ry - ly, 0.0f);
    float inter = w * h;
    return inter / (aar + bar - inter);
}

// ---------------- kernel 1: per-image pipeline ----------------
// 128 threads. Group A = warps 0-1 (t<64), Group B = warps 2-3.
__global__ __launch_bounds__(128) void k_per_image(const float* __restrict__ tgt,
                                                   const float* __restrict__ outp) {
    int img = blockIdx.x;
    int t = threadIdx.x;
    int tb = t - 64;                 // B-group local index

    __shared__ __align__(16) float stageP[1470];   // pred tensor stage; aliased after P1
    __shared__ __align__(16) float stageT[1470];   // target tensor stage
    __shared__ float uconf[NB];
    __shared__ __align__(16) float4 ubox[NB];      // unsorted pred boxes
    __shared__ __align__(8)  float2 ucombo[NB];    // unsorted (area, cls bits)
    __shared__ __align__(16) float4 sbox[NB];      // sorted pred boxes
    __shared__ __align__(8)  float2 scombo[NB];    // sorted (area, cls bits)
    __shared__ __align__(16) float4 gbox[NB];      // GT boxes
    __shared__ float garea[NB];
    __shared__ int sbest[NB];                      // best GT index per sorted pred (-1 = none)
    __shared__ unsigned long long clsmask[NC];     // sorted-pred membership per class
    __shared__ unsigned long long gclsmask[NC];    // valid-GT membership per class
    __shared__ unsigned long long sh_conf, sh_valid, sh_tp;

    // aliases into stageP (pred stage dead after P1)
    unsigned long long* sup = (unsigned long long*)stageP;   // floats 0..97   (j>t bits only)
    int*   srcidx = (int*)(stageP + 98);                     // 98..146
    int*   ubest  = (int*)(stageP + 147);                    // 147..195
    int*   rhi    = (int*)(stageP + 196);                    // 196..244  (rank partial j in [25,49))
    unsigned* ballots = (unsigned*)(stageP + 245);           // 2 words

    if (t < NC) clsmask[t] = 0ull;
    else if (t >= 32 && t < 32 + NC) gclsmask[t - 32] = 0ull;
    else if (t == 63) sh_conf = 0ull;

    // ---- P0: stage both tensors (coalesced float2, 2 streams) ----
    {
        const float2* srcP = reinterpret_cast<const float2*>(outp) + (size_t)img * 735;
        const float2* srcT = reinterpret_cast<const float2*>(tgt)  + (size_t)img * 735;
        float2* dstP = reinterpret_cast<float2*>(stageP);
        float2* dstT = reinterpret_cast<float2*>(stageT);
        for (int i = t; i < 735; i += 128) { dstP[i] = srcP[i]; dstT[i] = srcT[i]; }
    }
    __syncthreads();

    // ---- P1: pred decode (A) || GT decode + class masks (B) ----
    float bx0 = 0.f, by0 = 0.f, bx1 = 0.f, by1 = 0.f, conf = 0.f, area = 0.f;
    int cls = 0;
    if (t < NB) {
        const float* o = stageP + t * DD;
        float c0 = sigm(o[4]);
        float c1 = sigm(o[9]);
        int resp = (c1 > c0) ? 1 : 0;
        conf = resp ? c1 : c0;
        const float* oc = o + resp * 5;
        float px = sigm(oc[0]), py = sigm(oc[1]), pw = sigm(oc[2]), ph = sigm(oc[3]);
        int iy = t / SS, jx = t % SS;
        float cx = (px + (float)jx) * 64.0f;
        float cy = (py + (float)iy) * 64.0f;
        float W = pw * 448.0f, H = ph * 448.0f;
        bx0 = cx - W * 0.5f; by0 = cy - H * 0.5f;
        bx1 = cx + W * 0.5f; by1 = cy + H * 0.5f;
        area = (bx1 - bx0) * (by1 - by0);
        uconf[t] = conf;
        float bm = o[10]; int bi = 0;
        #pragma unroll
        for (int k = 1; k < NC; k++) { float v = o[10 + k]; if (v > bm) { bm = v; bi = k; } }
        cls = bi;
        ubox[t] = make_float4(bx0, by0, bx1, by1);
        ucombo[t] = make_float2(area, __int_as_float(cls));
    } else if (tb >= 0 && tb < NB) {
        const float* g = stageT + tb * DD;
        int valid = (g[4] > 0.5f) ? 1 : 0;
        int iy = tb / SS, jx = tb % SS;
        float cx = (g[0] + (float)jx) * 64.0f;
        float cy = (g[1] + (float)iy) * 64.0f;
        float W = g[2] * 448.0f, H = g[3] * 448.0f;
        float x0 = cx - W * 0.5f, y0 = cy - H * 0.5f;
        float x1 = cx + W * 0.5f, y1 = cy + H * 0.5f;
        gbox[tb] = make_float4(x0, y0, x1, y1);
        garea[tb] = (x1 - x0) * (y1 - y0);
        float gm = g[10]; int gi = 0;
        #pragma unroll
        for (int k = 1; k < NC; k++) { float v = g[10 + k]; if (v > gm) { gm = v; gi = k; } }
        if (valid) atomicOr(&gclsmask[gi], 1ull << tb);
    }
    __syncthreads();

    // ---- P2: A: rank partial j<25 || B: GT-IoU bit-loop + rank partial j>=25 ----
    int r_lo = 0;
    if (t < NB) {
        float ci = conf;
        #pragma unroll
        for (int j = 0; j < 25; j++) {
            float cj = uconf[j];
            r_lo += (cj > ci) || (cj == ci && j < t);
        }
    } else if (tb >= 0 && tb < NB) {
        float4 a = ubox[tb];
        float2 ac = ucombo[tb];
        int c = __float_as_int(ac.y);
        unsigned long long m = gclsmask[c];
        float mx = -1.0f; int best = -1;
        while (m) {
            int g = __ffsll((long long)m) - 1;
            m &= m - 1ull;
            float v = iou_v(a.x, a.y, a.z, a.w, ac.x, gbox[g], garea[g]);
            if (v > mx) { mx = v; best = g; }
        }
        ubest[tb] = (mx > 0.5f) ? best : -1;

        float ci = uconf[tb];
        int rh = 0;
        #pragma unroll
        for (int j = 25; j < NB; j++) {
            float cj = uconf[j];
            rh += (cj > ci) || (cj == ci && j < tb);
        }
        rhi[tb] = rh;
    }
    __syncthreads();

    // ---- P3: A: combine ranks + scatter + masks ----
    if (t < NB) {
        int r = r_lo + rhi[t];
        sbox[r] = make_float4(bx0, by0, bx1, by1);
        scombo[r] = make_float2(area, __int_as_float(cls));
        srcidx[r] = t;
        atomicOr(&clsmask[cls], 1ull << r);
        if (conf > 0.5f) atomicOr(&sh_conf, 1ull << r);
    }
    __syncthreads();

    // ---- P4: NMS rows via clsmask bit-loop (j>t only) + sbest permute + cand ballot ----
    if (t < 64) {
        int bflag = 0;
        if (t < NB) {
            float4 a = sbox[t];
            float2 ac = scombo[t];
            int c = __float_as_int(ac.y);
            unsigned long long cand = clsmask[c] & ~((2ull << t) - 1ull);  // bits j>t
            unsigned long long m = 0ull;
            while (cand) {
                int j = __ffsll((long long)cand) - 1;
                cand &= cand - 1ull;
                if (iou_v(a.x, a.y, a.z, a.w, ac.x, sbox[j], scombo[j].x) > 0.5f)
                    m |= (1ull << j);
            }
            sup[t] = m;
            int b = ubest[srcidx[t]];
            sbest[t] = b;
            bflag = (b >= 0);
        }
        unsigned bc = __ballot_sync(0xffffffffu, bflag);
        if ((t & 31) == 0) ballots[t >> 5] = bc;
    }
    __syncthreads();

    // ---- P5: serial greedy NMS + TP matching via bit-scans (thread 0) ----
    if (t == 0) {
        unsigned long long candm = (unsigned long long)ballots[0] |
                                   ((unsigned long long)ballots[1] << 32);
        unsigned long long rem = (1ull << NB) - 1ull, keep = 0ull;
        while (rem) {
            int i = __ffsll((long long)rem) - 1;
            keep |= (1ull << i);
            rem &= ~(sup[i] | (1ull << i));
        }
        unsigned long long valid = keep & sh_conf;
        unsigned long long cand = valid & candm;
        unsigned long long matched = 0ull, tpm = 0ull;
        while (cand) {
            int i = __ffsll((long long)cand) - 1;
            cand &= cand - 1ull;
            int b = sbest[i];
            if (!((matched >> b) & 1ull)) {
                matched |= (1ull << b);
                tpm |= (1ull << i);
            }
        }
        sh_valid = valid; sh_tp = tpm;
    }
    __syncthreads();

    unsigned long long vm = sh_valid, tm = sh_tp;

    // ---- P6: records (A) || per-class counts incl. GT (B), all O(1) popcounts ----
    if (t < NB) {
        int rec = 0;
        if ((vm >> t) & 1ull) {
            int c = __float_as_int(scombo[t].y);
            unsigned long long cm = clsmask[c];
            int rank = __popcll(vm & cm & ((1ull << t) - 1ull));
            int tpc  = __popcll(tm & cm & ((2ull << t) - 1ull));
            int tp = (int)((tm >> t) & 1ull);
            rec = 0x40000000 | c | (rank << 8) | (tpc << 16) | (tp << 24);
        }
        g_records[img * NB + t] = rec;
    } else if (tb >= 0 && tb < NC) {
        unsigned long long cm = clsmask[tb];
        g_nvalid[tb * NBATCH + img] = __popcll(vm & cm);
        g_ntp[tb * NBATCH + img]    = __popcll(tm & cm);
        g_ngt[tb * NBATCH + img]    = __popcll(gclsmask[tb]);
    }
}

// ---------------- kernel 2: scans (nvalid, ntp) + GT totals + g_ap zero ----------------
__global__ __launch_bounds__(1024) void k_scan() {
    __shared__ int wsum[32];
    int bx = blockIdx.x;            // 0..59
    int t = threadIdx.x;            // 1024 threads x 4 elems = 4096

    if (bx == 0 && t < NC) g_ap[t] = 0.0;

    const int* in;
    if (bx < NC)          in = g_nvalid + bx * NBATCH;
    else if (bx < 2 * NC) in = g_ntp + (bx - NC) * NBATCH;
    else                  in = g_ngt + (bx - 2 * NC) * NBATCH;

    int4 v = reinterpret_cast<const int4*>(in)[t];
    int e1 = v.x, e2 = e1 + v.y, e3 = e2 + v.z;
    int sum = e3 + v.w;

    int lane = t & 31, wid = t >> 5;
    int x = sum;
    #pragma unroll
    for (int off = 1; off < 32; off <<= 1) {
        int y = __shfl_up_sync(0xffffffffu, x, off);
        if (lane >= off) x += y;
    }
    if (lane == 31) wsum[wid] = x;
    __syncthreads();
    if (wid == 0) {
        int w = wsum[lane];
        #pragma unroll
        for (int off = 1; off < 32; off <<= 1) {
            int y = __shfl_up_sync(0xffffffffu, w, off);
            if (lane >= off) w += y;
        }
        wsum[lane] = w;
    }
    __syncthreads();
    int pre = x - sum + ((wid > 0) ? wsum[wid - 1] : 0);   // exclusive prefix for elem 0

    if (bx < 2 * NC) {
        int* out = (bx < NC) ? (g_offv + bx * NBATCH) : (g_offt + (bx - NC) * NBATCH);
        int4 o;
        o.x = pre;
        o.y = pre + e1;
        o.z = pre + e2;
        o.w = pre + e3;
        reinterpret_cast<int4*>(out)[t] = o;
    } else {
        if (t == 1023) g_gt[bx - 2 * NC] = pre + sum;      // grand total
    }
}

// ---------------- kernel 3: AP term accumulation + fused finalize (last block) ----------------
__global__ __launch_bounds__(256) void k_ap(float* __restrict__ out) {
    int idx = blockIdx.x * blockDim.x + threadIdx.x;       // grid covers exactly NBATCH*NB
    int rec = g_records[idx];

    // need both the valid flag (bit 30) and tp (bit 24)
    if ((rec & 0x41000000) == 0x41000000) {
        int c = rec & 0xFF;
        int rank = (rec >> 8) & 0xFF;
        int tpc_loc = (rec >> 16) & 0xFF;
        int img = idx / NB;

        int j = g_offv[c * NBATCH + img] + rank + 1;      // 1-based global valid rank
        int tpc = g_offt[c * NBATCH + img] + tpc_loc;     // inclusive cumulative TP

        float pj = (float)tpc / ((float)j + 1e-6f);
        float pprev;
        if (j == 1) {
            pprev = (idx == 0) ? 1.0f : 0.0f;             // only global position 0 sees prepended p=1
        } else {
            pprev = (float)(tpc - 1) / ((float)(j - 1) + 1e-6f);
        }
        float gt = (float)g_gt[c];
        double term = (double)(pj + pprev) * 0.5 / (double)(gt + 1e-6f);
        atomicAdd(&g_ap[c], term);
    }

    // ---- last-block-done finalize ----
    __shared__ int sticket;
    __syncthreads();
    if (threadIdx.x == 0) {
        __threadfence();
        sticket = atomicAdd(&g_done, 1);
    }
    __syncthreads();
    if (sticket == AP_GRID - 1 && threadIdx.x < 32) {
        __threadfence();
        int lane = threadIdx.x;
        double a = 0.0; int has = 0;
        if (lane < NC) {
            has = (g_gt[lane] > 0);
            if (has) a = __ldcg(&g_ap[lane]);             // bypass L1 (values written via L2 atomics)
        }
        unsigned hb = __ballot_sync(0xffffffffu, has);
        #pragma unroll
        for (int off = 16; off > 0; off >>= 1)
            a += __shfl_down_sync(0xffffffffu, a, off);
        if (lane == 0) {
            int n = __popc(hb);
            double nh = (n > 0) ? (double)n : 1.0;
            out[0] = (float)(a / nh);
            g_done = 0;                                   // reset for next graph replay
        }
    }
}

// ---------------- launcher ----------------
extern "C" void kernel_launch(void* const* d_in, const int* in_sizes, int n_in,
                              void* d_out, int out_size) {
    const float* tgt = (const float*)d_in[0];
    const float* outp = (const float*)d_in[1];
    float* out = (float*)d_out;

    k_per_image<<<NBATCH, 128>>>(tgt, outp);
    k_scan<<<60, 1024>>>();
    k_ap<<<AP_GRID, 256>>>(out);
}

// round 12
// speedup vs baseline: 1.2953x; 1.2953x over previous
#include <cuda_runtime.h>
#include <math.h>

#define SS 7
#define NB 49          // boxes per image
#define NC 20          // classes
#define NBATCH 4096
#define DD 30          // channels per cell

#define AP_GRID 784    // 784 * 256 = 200704 = NBATCH*NB exactly

// ---------------- scratch (device globals; no allocation) ----------------
__device__ __align__(256) int    g_records[NBATCH * NB];   // packed per-pred record
__device__ __align__(256) int    g_nvalid[NC * NBATCH];    // per class, per image valid count
__device__ __align__(256) int    g_ntp[NC * NBATCH];       // per class, per image tp count
__device__ __align__(256) int    g_ngt[NC * NBATCH];       // per class, per image GT count
__device__ __align__(256) int    g_offv[NC * NBATCH];      // exclusive scans over images
__device__ __align__(256) int    g_offt[NC * NBATCH];
__device__ int    g_gt[NC];                                // per-class GT totals (from k_scan)
__device__ double g_ap[NC];                                // per-class AP accumulators
__device__ int    g_done;                                  // k_ap ticket (0 at start; reset by last block)

// ---------------- helpers ----------------
__device__ __forceinline__ float sigm(float x) { return 1.0f / (1.0f + expf(-x)); }

__device__ __forceinline__ float iou_v(float ax0, float ay0, float ax1, float ay1, float aar,
                                       float4 b, float bar) {
    float lx = fmaxf(ax0, b.x), ly = fmaxf(ay0, b.y);
    float rx = fminf(ax1, b.z), ry = fminf(ay1, b.w);
    float w = fmaxf(rx - lx, 0.0f), h = fmaxf(ry - ly, 0.0f);
    float inter = w * h;
    return inter / (aar + bar - inter);
}

// argmax over 20 channels, strict > (first index wins ties), float2-vectorized.
// base must be 8B-aligned (true: byte offset 120*t + 40).
__device__ __forceinline__ int argmax20(const float* base) {
    const float2* p2 = reinterpret_cast<const float2*>(base);
    float bm = -3.0e38f; int bi = 0;
    #pragma unroll
    for (int k2 = 0; k2 < 10; k2++) {
        float2 v = p2[k2];
        float m  = (v.y > v.x) ? v.y : v.x;         // within-pair: lower index on tie
        int   mi = (v.y > v.x) ? (2 * k2 + 1) : (2 * k2);
        if (m > bm) { bm = m; bi = mi; }            // across pairs: first max wins
    }
    return bi;
}

// ---------------- kernel 1: per-image pipeline ----------------
// 128 threads. Group A = warps 0-1 (t<64), Group B = warps 2-3.
__global__ __launch_bounds__(128) void k_per_image(const float* __restrict__ tgt,
                                                   const float* __restrict__ outp) {
    int img = blockIdx.x;
    int t = threadIdx.x;
    int tb = t - 64;                 // B-group local index

    __shared__ __align__(16) float stageP[1470];   // pred tensor stage; aliased after P1
    __shared__ __align__(16) float stageT[1470];   // target tensor stage
    __shared__ __align__(8)  float uconf[50];      // [49] = -1 pad for float2 rank loop
    __shared__ __align__(16) float4 sbox[NB];      // sorted pred boxes
    __shared__ __align__(8)  float2 scombo[NB];    // sorted (area, cls bits)
    __shared__ __align__(16) float4 gbox[NB];      // GT boxes
    __shared__ float garea[NB];
    __shared__ int sbest[NB];                      // best GT index per sorted pred (-1 = none)
    __shared__ unsigned long long clsmask[NC];     // sorted-pred membership per class
    __shared__ unsigned long long gclsmask[NC];    // valid-GT membership per class
    __shared__ unsigned long long sh_conf, sh_valid, sh_tp;

    // aliases into stageP (pred stage dead after P1)
    unsigned long long* sup = (unsigned long long*)stageP;   // floats 0..97  (j>t bits only)
    unsigned* ballots = (unsigned*)(stageP + 98);            // 4 words: [0..1]=W, [2..3]=cand

    if (t < NC) clsmask[t] = 0ull;
    else if (t >= 32 && t < 32 + NC) gclsmask[t - 32] = 0ull;
    else if (t == 63) sh_conf = 0ull;

    // ---- P0: stage both tensors (coalesced float2, 2 streams) ----
    {
        const float2* srcP = reinterpret_cast<const float2*>(outp) + (size_t)img * 735;
        const float2* srcT = reinterpret_cast<const float2*>(tgt)  + (size_t)img * 735;
        float2* dstP = reinterpret_cast<float2*>(stageP);
        float2* dstT = reinterpret_cast<float2*>(stageT);
        for (int i = t; i < 735; i += 128) { dstP[i] = srcP[i]; dstT[i] = srcT[i]; }
    }
    __syncthreads();

    // ---- P1: pred decode (A) || GT decode + class masks (B) ----
    float bx0 = 0.f, by0 = 0.f, bx1 = 0.f, by1 = 0.f, conf = 0.f, area = 0.f;
    int cls = 0;
    if (t < NB) {
        const float* o = stageP + t * DD;
        float c0 = sigm(o[4]);
        float c1 = sigm(o[9]);
        int resp = (c1 > c0) ? 1 : 0;
        conf = resp ? c1 : c0;
        const float* oc = o + resp * 5;
        float px = sigm(oc[0]), py = sigm(oc[1]), pw = sigm(oc[2]), ph = sigm(oc[3]);
        int iy = t / SS, jx = t % SS;
        float cx = (px + (float)jx) * 64.0f;
        float cy = (py + (float)iy) * 64.0f;
        float W = pw * 448.0f, H = ph * 448.0f;
        bx0 = cx - W * 0.5f; by0 = cy - H * 0.5f;
        bx1 = cx + W * 0.5f; by1 = cy + H * 0.5f;
        area = (bx1 - bx0) * (by1 - by0);
        uconf[t] = conf;
        cls = argmax20(o + 10);
    } else if (t == NB) {
        uconf[NB] = -1.0f;                       // pad (conf > 0 always; never matches)
    } else if (tb >= 0 && tb < NB) {
        const float* g = stageT + tb * DD;
        int valid = (g[4] > 0.5f) ? 1 : 0;
        int iy = tb / SS, jx = tb % SS;
        float cx = (g[0] + (float)jx) * 64.0f;
        float cy = (g[1] + (float)iy) * 64.0f;
        float W = g[2] * 448.0f, H = g[3] * 448.0f;
        float x0 = cx - W * 0.5f, y0 = cy - H * 0.5f;
        float x1 = cx + W * 0.5f, y1 = cy + H * 0.5f;
        gbox[tb] = make_float4(x0, y0, x1, y1);
        garea[tb] = (x1 - x0) * (y1 - y0);
        int gi = argmax20(g + 10);
        if (valid) atomicOr(&gclsmask[gi], 1ull << tb);
    }
    __syncthreads();

    // ---- P2: A: stable rank (float2) + scatter + masks ----
    if (t < NB) {
        float ci = conf;
        int r = 0;
        const float2* u2 = reinterpret_cast<const float2*>(uconf);
        #pragma unroll
        for (int j2 = 0; j2 < 25; j2++) {
            float2 v = u2[j2];
            int j0 = j2 * 2;
            r += (v.x > ci) || ((v.x == ci) && (j0 < t));
            r += (v.y > ci) || ((v.y == ci) && (j0 + 1 < t));
        }
        sbox[r] = make_float4(bx0, by0, bx1, by1);
        scombo[r] = make_float2(area, __int_as_float(cls));
        atomicOr(&clsmask[cls], 1ull << r);
        if (ci > 0.5f) atomicOr(&sh_conf, 1ull << r);
    }
    __syncthreads();

    // ---- P3: A: NMS rows (sparse bit-loop, j>t)  ||  B: GT-IoU in sorted space ----
    if (t < 64) {
        int wflag = 0;
        if (t < NB) {
            float4 a = sbox[t];
            float2 ac = scombo[t];
            int c = __float_as_int(ac.y);
            unsigned long long cand = clsmask[c] & ~((2ull << t) - 1ull);  // bits j>t
            unsigned long long m = 0ull;
            while (cand) {
                int j = __ffsll((long long)cand) - 1;
                cand &= cand - 1ull;
                if (iou_v(a.x, a.y, a.z, a.w, ac.x, sbox[j], scombo[j].x) > 0.5f)
                    m |= (1ull << j);
            }
            sup[t] = m;
            wflag = (m != 0ull);
        }
        unsigned bc = __ballot_sync(0xffffffffu, wflag);
        if ((t & 31) == 0) ballots[t >> 5] = bc;
    } else {
        int cflag = 0;
        if (tb < NB) {
            float4 a = sbox[tb];
            float2 ac = scombo[tb];
            int c = __float_as_int(ac.y);
            unsigned long long m = gclsmask[c];
            float mx = -1.0f; int best = -1;
            while (m) {
                int g = __ffsll((long long)m) - 1;
                m &= m - 1ull;
                float v = iou_v(a.x, a.y, a.z, a.w, ac.x, gbox[g], garea[g]);
                if (v > mx) { mx = v; best = g; }
            }
            int b = (mx > 0.5f) ? best : -1;
            sbest[tb] = b;
            cflag = (b >= 0);
        }
        unsigned bc = __ballot_sync(0xffffffffu, cflag);
        if ((tb & 31) == 0) ballots[2 + (tb >> 5)] = bc;
    }
    __syncthreads();

    // ---- P4: serial greedy NMS over NONZERO rows only + TP matching (thread 0) ----
    if (t == 0) {
        unsigned long long wm = (unsigned long long)ballots[0] |
                                ((unsigned long long)ballots[1] << 32);
        unsigned long long candm = (unsigned long long)ballots[2] |
                                   ((unsigned long long)ballots[3] << 32);
        unsigned long long rem = (1ull << NB) - 1ull;
        while (wm) {                                   // only rows that can suppress
            int i = __ffsll((long long)wm) - 1;
            wm &= wm - 1ull;
            if ((rem >> i) & 1ull) rem &= ~sup[i];     // sup[i] has only j>i bits
        }
        unsigned long long valid = rem & sh_conf;      // rem == keep
        unsigned long long cand = valid & candm;
        unsigned long long matched = 0ull, tpm = 0ull;
        while (cand) {
            int i = __ffsll((long long)cand) - 1;
            cand &= cand - 1ull;
            int b = sbest[i];
            if (!((matched >> b) & 1ull)) {
                matched |= (1ull << b);
                tpm |= (1ull << i);
            }
        }
        sh_valid = valid; sh_tp = tpm;
    }
    __syncthreads();

    unsigned long long vm = sh_valid, tm = sh_tp;

    // ---- P5: records (A) || per-class counts incl. GT (B), all O(1) popcounts ----
    if (t < NB) {
        int rec = 0;
        if ((vm >> t) & 1ull) {
            int c = __float_as_int(scombo[t].y);
            unsigned long long cm = clsmask[c];
            int rank = __popcll(vm & cm & ((1ull << t) - 1ull));
            int tpc  = __popcll(tm & cm & ((2ull << t) - 1ull));
            int tp = (int)((tm >> t) & 1ull);
            rec = 0x40000000 | c | (rank << 8) | (tpc << 16) | (tp << 24);
        }
        g_records[img * NB + t] = rec;
    } else if (tb >= 0 && tb < NC) {
        unsigned long long cm = clsmask[tb];
        g_nvalid[tb * NBATCH + img] = __popcll(vm & cm);
        g_ntp[tb * NBATCH + img]    = __popcll(tm & cm);
        g_ngt[tb * NBATCH + img]    = __popcll(gclsmask[tb]);
    }
}

// ---------------- kernel 2: scans (nvalid, ntp) + GT totals + g_ap zero ----------------
__global__ __launch_bounds__(1024) void k_scan() {
    __shared__ int wsum[32];
    int bx = blockIdx.x;            // 0..59
    int t = threadIdx.x;            // 1024 threads x 4 elems = 4096

    if (bx == 0 && t < NC) g_ap[t] = 0.0;

    const int* in;
    if (bx < NC)          in = g_nvalid + bx * NBATCH;
    else if (bx < 2 * NC) in = g_ntp + (bx - NC) * NBATCH;
    else                  in = g_ngt + (bx - 2 * NC) * NBATCH;

    int4 v = reinterpret_cast<const int4*>(in)[t];
    int e1 = v.x, e2 = e1 + v.y, e3 = e2 + v.z;
    int sum = e3 + v.w;

    int lane = t & 31, wid = t >> 5;
    int x = sum;
    #pragma unroll
    for (int off = 1; off < 32; off <<= 1) {
        int y = __shfl_up_sync(0xffffffffu, x, off);
        if (lane >= off) x += y;
    }
    if (lane == 31) wsum[wid] = x;
    __syncthreads();
    if (wid == 0) {
        int w = wsum[lane];
        #pragma unroll
        for (int off = 1; off < 32; off <<= 1) {
            int y = __shfl_up_sync(0xffffffffu, w, off);
            if (lane >= off) w += y;
        }
        wsum[lane] = w;
    }
    __syncthreads();
    int pre = x - sum + ((wid > 0) ? wsum[wid - 1] : 0);   // exclusive prefix for elem 0

    if (bx < 2 * NC) {
        int* out = (bx < NC) ? (g_offv + bx * NBATCH) : (g_offt + (bx - NC) * NBATCH);
        int4 o;
        o.x = pre;
        o.y = pre + e1;
        o.z = pre + e2;
        o.w = pre + e3;
        reinterpret_cast<int4*>(out)[t] = o;
    } else {
        if (t == 1023) g_gt[bx - 2 * NC] = pre + sum;      // grand total
    }
}

// ---------------- kernel 3: AP term accumulation + fused finalize (last block) ----------------
__global__ __launch_bounds__(256) void k_ap(float* __restrict__ out) {
    int idx = blockIdx.x * blockDim.x + threadIdx.x;       // grid covers exactly NBATCH*NB

    int rec = g_records[idx];
    if ((rec & 0x41000000) == 0x41000000) {                // valid flag + tp
        int c = rec & 0xFF;
        int rank = (rec >> 8) & 0xFF;
        int tpc_loc = (rec >> 16) & 0xFF;
        int img = idx / NB;

        int j = g_offv[c * NBATCH + img] + rank + 1;      // 1-based global valid rank
        int tpc = g_offt[c * NBATCH + img] + tpc_loc;     // inclusive cumulative TP

        float pj = (float)tpc / ((float)j + 1e-6f);
        float pprev;
        if (j == 1) {
            pprev = (idx == 0) ? 1.0f : 0.0f;             // only global pos 0 sees prepended p=1
        } else {
            pprev = (float)(tpc - 1) / ((float)(j - 1) + 1e-6f);
        }
        float gt = (float)g_gt[c];
        double term = (double)(pj + pprev) * 0.5 / (double)(gt + 1e-6f);
        atomicAdd(&g_ap[c], term);
    }

    // ---- last-block-done finalize ----
    __shared__ int sticket;
    __syncthreads();
    if (threadIdx.x == 0) {
        __threadfence();
        sticket = atomicAdd(&g_done, 1);
    }
    __syncthreads();
    if (sticket == AP_GRID - 1 && threadIdx.x < 32) {
        __threadfence();
        int lane = threadIdx.x;
        double a = 0.0; int has = 0;
        if (lane < NC) {
            has = (g_gt[lane] > 0);
            if (has) a = __ldcg(&g_ap[lane]);             // bypass L1 (written via L2 atomics)
        }
        unsigned hb = __ballot_sync(0xffffffffu, has);
        #pragma unroll
        for (int off = 16; off > 0; off >>= 1)
            a += __shfl_down_sync(0xffffffffu, a, off);
        if (lane == 0) {
            int n = __popc(hb);
            double nh = (n > 0) ? (double)n : 1.0;
            out[0] = (float)(a / nh);
            g_done = 0;                                   // reset for next graph replay
        }
    }
}

// ---------------- launcher ----------------
extern "C" void kernel_launch(void* const* d_in, const int* in_sizes, int n_in,
                              void* d_out, int out_size) {
    const float* tgt = (const float*)d_in[0];
    const float* outp = (const float*)d_in[1];
    float* out = (float*)d_out;

    k_per_image<<<NBATCH, 128>>>(tgt, outp);
    k_scan<<<60, 1024>>>();
    k_ap<<<AP_GRID, 256>>>(out);
}

// round 13
// speedup vs baseline: 1.4081x; 1.0871x over previous
#include <cuda_runtime.h>
#include <math.h>

#define SS 7
#define NB 49          // boxes per image
#define NC 20          // classes
#define NBATCH 4096
#define DD 30          // channels per cell

#define AP_GRID 784    // 784 * 256 = 200704 = NBATCH*NB exactly

// ---------------- scratch (device globals; no allocation) ----------------
__device__ __align__(256) int    g_records[NBATCH * NB];   // packed per-pred record
__device__ __align__(256) int    g_nvalid[NC * NBATCH];    // per class, per image valid count
__device__ __align__(256) int    g_ntp[NC * NBATCH];       // per class, per image tp count
__device__ __align__(256) int    g_ngt[NC * NBATCH];       // per class, per image GT count
__device__ __align__(256) int    g_offv[NC * NBATCH];      // exclusive scans over images
__device__ __align__(256) int    g_offt[NC * NBATCH];
__device__ int    g_gt[NC];                                // per-class GT totals (from k_scan)
__device__ double g_ap[NC];                                // per-class AP accumulators
__device__ int    g_done;                                  // k_ap ticket (0 at start; reset by last block)

// ---------------- helpers ----------------
__device__ __forceinline__ float sigm(float x) {
    // monotone fast sigmoid; feeds comparisons only
    return __fdividef(1.0f, 1.0f + __expf(-x));
}

__device__ __forceinline__ float iou_v(float ax0, float ay0, float ax1, float ay1, float aar,
                                       float4 b, float bar) {
    float lx = fmaxf(ax0, b.x), ly = fmaxf(ay0, b.y);
    float rx = fminf(ax1, b.z), ry = fminf(ay1, b.w);
    float w = fmaxf(rx - lx, 0.0f), h = fmaxf(ry - ly, 0.0f);
    float inter = w * h;
    return inter / (aar + bar - inter);
}

// IoU > 0.5 test without division (union > 0 guaranteed: all boxes well-formed)
__device__ __forceinline__ bool iou_gt_half(float ax0, float ay0, float ax1, float ay1, float aar,
                                            float4 b, float bar) {
    float lx = fmaxf(ax0, b.x), ly = fmaxf(ay0, b.y);
    float rx = fminf(ax1, b.z), ry = fminf(ay1, b.w);
    float w = fmaxf(rx - lx, 0.0f), h = fmaxf(ry - ly, 0.0f);
    float inter = w * h;
    return 2.0f * inter > (aar + bar - inter);
}

// argmax over 20 channels, strict > (first index wins ties), float2-vectorized.
__device__ __forceinline__ int argmax20(const float* base) {
    const float2* p2 = reinterpret_cast<const float2*>(base);
    float bm = -3.0e38f; int bi = 0;
    #pragma unroll
    for (int k2 = 0; k2 < 10; k2++) {
        float2 v = p2[k2];
        float m  = (v.y > v.x) ? v.y : v.x;         // within-pair: lower index on tie
        int   mi = (v.y > v.x) ? (2 * k2 + 1) : (2 * k2);
        if (m > bm) { bm = m; bi = mi; }            // across pairs: first max wins
    }
    return bi;
}

// ---------------- kernel 1: per-image pipeline ----------------
// 128 threads. Group A = warps 0-1 (t<64), Group B = warps 2-3.
__global__ __launch_bounds__(128, 16) void k_per_image(const float* __restrict__ tgt,
                                                       const float* __restrict__ outp) {
    int img = blockIdx.x;
    int t = threadIdx.x;
    int tb = t - 64;                 // B-group local index

    __shared__ __align__(16) float stageP[1470];   // pred tensor stage; aliased after P1
    __shared__ __align__(16) float stageT[1470];   // target tensor stage; aliased after P1
    __shared__ __align__(8)  float uconf[50];      // [49] = -1 pad for float2 rank loop
    __shared__ __align__(16) float4 gbox[NB];      // GT boxes
    __shared__ float garea[NB];
    __shared__ unsigned long long clsmask[NC];     // sorted-pred membership per class
    __shared__ unsigned long long gclsmask[NC];    // valid-GT membership per class
    __shared__ unsigned long long sh_conf, sh_valid, sh_tp;

    // aliases into stageP (dead after P1 barrier)
    unsigned long long* sup = (unsigned long long*)stageP;   // floats 0..97  (j>t bits only)
    unsigned* ballots = (unsigned*)(stageP + 98);            // 4 words: [0..1]=W, [2..3]=cand
    // aliases into stageT (dead after P1 barrier)
    float4* sbox   = (float4*)stageT;                        // floats 0..195   sorted boxes
    float2* scombo = (float2*)(stageT + 196);                // 196..293  (area, cls bits)
    int*    sbest  = (int*)(stageT + 294);                   // 294..342  best GT (-1 = none)

    if (t < NC) clsmask[t] = 0ull;
    else if (t >= 32 && t < 32 + NC) gclsmask[t - 32] = 0ull;
    else if (t == 63) sh_conf = 0ull;

    // ---- P0: stage both tensors (coalesced float2, 2 streams) ----
    {
        const float2* srcP = reinterpret_cast<const float2*>(outp) + (size_t)img * 735;
        const float2* srcT = reinterpret_cast<const float2*>(tgt)  + (size_t)img * 735;
        float2* dstP = reinterpret_cast<float2*>(stageP);
        float2* dstT = reinterpret_cast<float2*>(stageT);
        for (int i = t; i < 735; i += 128) { dstP[i] = srcP[i]; dstT[i] = srcT[i]; }
    }
    __syncthreads();

    // ---- P1: pred decode (A) || GT decode + class masks (B) ----
    float bx0 = 0.f, by0 = 0.f, bx1 = 0.f, by1 = 0.f, conf = 0.f, area = 0.f;
    int cls = 0;
    if (t < NB) {
        const float* o = stageP + t * DD;
        float c0 = sigm(o[4]);
        float c1 = sigm(o[9]);
        int resp = (c1 > c0) ? 1 : 0;
        conf = resp ? c1 : c0;
        const float* oc = o + resp * 5;
        float px = sigm(oc[0]), py = sigm(oc[1]), pw = sigm(oc[2]), ph = sigm(oc[3]);
        int iy = t / SS, jx = t % SS;
        float cx = (px + (float)jx) * 64.0f;
        float cy = (py + (float)iy) * 64.0f;
        float W = pw * 448.0f, H = ph * 448.0f;
        bx0 = cx - W * 0.5f; by0 = cy - H * 0.5f;
        bx1 = cx + W * 0.5f; by1 = cy + H * 0.5f;
        area = (bx1 - bx0) * (by1 - by0);
        uconf[t] = conf;
        cls = argmax20(o + 10);
    } else if (t == NB) {
        uconf[NB] = -1.0f;                       // pad (conf > 0 always; never matches)
    } else if (tb >= 0 && tb < NB) {
        const float* g = stageT + tb * DD;
        int valid = (g[4] > 0.5f) ? 1 : 0;
        int iy = tb / SS, jx = tb % SS;
        float cx = (g[0] + (float)jx) * 64.0f;
        float cy = (g[1] + (float)iy) * 64.0f;
        float W = g[2] * 448.0f, H = g[3] * 448.0f;
        float x0 = cx - W * 0.5f, y0 = cy - H * 0.5f;
        float x1 = cx + W * 0.5f, y1 = cy + H * 0.5f;
        gbox[tb] = make_float4(x0, y0, x1, y1);
        garea[tb] = (x1 - x0) * (y1 - y0);
        int gi = argmax20(g + 10);
        if (valid) atomicOr(&gclsmask[gi], 1ull << tb);
    }
    __syncthreads();   // stageP/stageT dead past here (all consumers done)

    // ---- P2: A: stable rank (float2) + scatter + masks ----
    if (t < NB) {
        float ci = conf;
        int r = 0;
        const float2* u2 = reinterpret_cast<const float2*>(uconf);
        #pragma unroll
        for (int j2 = 0; j2 < 25; j2++) {
            float2 v = u2[j2];
            int j0 = j2 * 2;
            r += (v.x > ci) || ((v.x == ci) && (j0 < t));
            r += (v.y > ci) || ((v.y == ci) && (j0 + 1 < t));
        }
        sbox[r] = make_float4(bx0, by0, bx1, by1);
        scombo[r] = make_float2(area, __int_as_float(cls));
        atomicOr(&clsmask[cls], 1ull << r);
        if (ci > 0.5f) atomicOr(&sh_conf, 1ull << r);
    }
    __syncthreads();

    // ---- P3: A: NMS rows (sparse bit-loop, j>t)  ||  B: GT-IoU in sorted space ----
    if (t < 64) {
        int wflag = 0;
        if (t < NB) {
            float4 a = sbox[t];
            float2 ac = scombo[t];
            int c = __float_as_int(ac.y);
            unsigned long long cand = clsmask[c] & ~((2ull << t) - 1ull);  // bits j>t
            unsigned long long m = 0ull;
            while (cand) {
                int j = __ffsll((long long)cand) - 1;
                cand &= cand - 1ull;
                if (iou_gt_half(a.x, a.y, a.z, a.w, ac.x, sbox[j], scombo[j].x))
                    m |= (1ull << j);
            }
            sup[t] = m;
            wflag = (m != 0ull);
        }
        unsigned bc = __ballot_sync(0xffffffffu, wflag);
        if ((t & 31) == 0) ballots[t >> 5] = bc;
    } else {
        int cflag = 0;
        if (tb < NB) {
            float4 a = sbox[tb];
            float2 ac = scombo[tb];
            int c = __float_as_int(ac.y);
            unsigned long long m = gclsmask[c];
            float mx = -1.0f; int best = -1;
            while (m) {
                int g = __ffsll((long long)m) - 1;
                m &= m - 1ull;
                float v = iou_v(a.x, a.y, a.z, a.w, ac.x, gbox[g], garea[g]);
                if (v > mx) { mx = v; best = g; }
            }
            int b = (mx > 0.5f) ? best : -1;
            sbest[tb] = b;
            cflag = (b >= 0);
        }
        unsigned bc = __ballot_sync(0xffffffffu, cflag);
        if ((tb & 31) == 0) ballots[2 + (tb >> 5)] = bc;
    }
    __syncthreads();

    // ---- P4: serial greedy NMS over NONZERO rows only + TP matching (thread 0) ----
    if (t == 0) {
        unsigned long long wm = (unsigned long long)ballots[0] |
                                ((unsigned long long)ballots[1] << 32);
        unsigned long long candm = (unsigned long long)ballots[2] |
                                   ((unsigned long long)ballots[3] << 32);
        unsigned long long rem = (1ull << NB) - 1ull;
        while (wm) {                                   // only rows that can suppress
            int i = __ffsll((long long)wm) - 1;
            wm &= wm - 1ull;
            if ((rem >> i) & 1ull) rem &= ~sup[i];     // sup[i] has only j>i bits
        }
        unsigned long long valid = rem & sh_conf;      // rem == keep
        unsigned long long cand = valid & candm;
        unsigned long long matched = 0ull, tpm = 0ull;
        while (cand) {
            int i = __ffsll((long long)cand) - 1;
            cand &= cand - 1ull;
            int b = sbest[i];
            if (!((matched >> b) & 1ull)) {
                matched |= (1ull << b);
                tpm |= (1ull << i);
            }
        }
        sh_valid = valid; sh_tp = tpm;
    }
    __syncthreads();

    unsigned long long vm = sh_valid, tm = sh_tp;

    // ---- P5: records (A) || per-class counts incl. GT (B), all O(1) popcounts ----
    if (t < NB) {
        int rec = 0;
        if ((vm >> t) & 1ull) {
            int c = __float_as_int(scombo[t].y);
            unsigned long long cm = clsmask[c];
            int rank = __popcll(vm & cm & ((1ull << t) - 1ull));
            int tpc  = __popcll(tm & cm & ((2ull << t) - 1ull));
            int tp = (int)((tm >> t) & 1ull);
            rec = 0x40000000 | c | (rank << 8) | (tpc << 16) | (tp << 24);
        }
        g_records[img * NB + t] = rec;
    } else if (tb >= 0 && tb < NC) {
        unsigned long long cm = clsmask[tb];
        g_nvalid[tb * NBATCH + img] = __popcll(vm & cm);
        g_ntp[tb * NBATCH + img]    = __popcll(tm & cm);
        g_ngt[tb * NBATCH + img]    = __popcll(gclsmask[tb]);
    }
}

// ---------------- kernel 2: scans (nvalid, ntp) + GT totals + g_ap zero ----------------
__global__ __launch_bounds__(1024) void k_scan() {
    __shared__ int wsum[32];
    int bx = blockIdx.x;            // 0..59
    int t = threadIdx.x;            // 1024 threads x 4 elems = 4096

    if (bx == 0 && t < NC) g_ap[t] = 0.0;

    const int* in;
    if (bx < NC)          in = g_nvalid + bx * NBATCH;
    else if (bx < 2 * NC) in = g_ntp + (bx - NC) * NBATCH;
    else                  in = g_ngt + (bx - 2 * NC) * NBATCH;

    int4 v = reinterpret_cast<const int4*>(in)[t];
    int e1 = v.x, e2 = e1 + v.y, e3 = e2 + v.z;
    int sum = e3 + v.w;

    int lane = t & 31, wid = t >> 5;
    int x = sum;
    #pragma unroll
    for (int off = 1; off < 32; off <<= 1) {
        int y = __shfl_up_sync(0xffffffffu, x, off);
        if (lane >= off) x += y;
    }
    if (lane == 31) wsum[wid] = x;
    __syncthreads();
    if (wid == 0) {
        int w = wsum[lane];
        #pragma unroll
        for (int off = 1; off < 32; off <<= 1) {
            int y = __shfl_up_sync(0xffffffffu, w, off);
            if (lane >= off) w += y;
        }
        wsum[lane] = w;
    }
    __syncthreads();
    int pre = x - sum + ((wid > 0) ? wsum[wid - 1] : 0);   // exclusive prefix for elem 0

    if (bx < 2 * NC) {
        int* out = (bx < NC) ? (g_offv + bx * NBATCH) : (g_offt + (bx - NC) * NBATCH);
        int4 o;
        o.x = pre;
        o.y = pre + e1;
        o.z = pre + e2;
        o.w = pre + e3;
        reinterpret_cast<int4*>(out)[t] = o;
    } else {
        if (t == 1023) g_gt[bx - 2 * NC] = pre + sum;      // grand total
    }
}

// ---------------- kernel 3: AP term accumulation + fused finalize (last block) ----------------
__global__ __launch_bounds__(256) void k_ap(float* __restrict__ out) {
    int idx = blockIdx.x * blockDim.x + threadIdx.x;       // grid covers exactly NBATCH*NB

    int rec = g_records[idx];
    if ((rec & 0x41000000) == 0x41000000) {                // valid flag + tp
        int c = rec & 0xFF;
        int rank = (rec >> 8) & 0xFF;
        int tpc_loc = (rec >> 16) & 0xFF;
        int img = idx / NB;

        int j = g_offv[c * NBATCH + img] + rank + 1;      // 1-based global valid rank
        int tpc = g_offt[c * NBATCH + img] + tpc_loc;     // inclusive cumulative TP

        float pj = (float)tpc / ((float)j + 1e-6f);
        float pprev;
        if (j == 1) {
            pprev = (idx == 0) ? 1.0f : 0.0f;             // only global pos 0 sees prepended p=1
        } else {
            pprev = (float)(tpc - 1) / ((float)(j - 1) + 1e-6f);
        }
        float gt = (float)g_gt[c];
        double term = (double)(pj + pprev) * 0.5 / (double)(gt + 1e-6f);
        atomicAdd(&g_ap[c], term);
    }

    // ---- last-block-done finalize ----
    __shared__ int sticket;
    __syncthreads();
    if (threadIdx.x == 0) {
        __threadfence();
        sticket = atomicAdd(&g_done, 1);
    }
    __syncthreads();
    if (sticket == AP_GRID - 1 && threadIdx.x < 32) {
        __threadfence();
        int lane = threadIdx.x;
        double a = 0.0; int has = 0;
        if (lane < NC) {
            has = (g_gt[lane] > 0);
            if (has) a = __ldcg(&g_ap[lane]);             // bypass L1 (written via L2 atomics)
        }
        unsigned hb = __ballot_sync(0xffffffffu, has);
        #pragma unroll
        for (int off = 16; off > 0; off >>= 1)
            a += __shfl_down_sync(0xffffffffu, a, off);
        if (lane == 0) {
            int n = __popc(hb);
            double nh = (n > 0) ? (double)n : 1.0;
            out[0] = (float)(a / nh);
            g_done = 0;                                   // reset for next graph replay
        }
    }
}

// ---------------- launcher ----------------
extern "C" void kernel_launch(void* const* d_in, const int* in_sizes, int n_in,
                              void* d_out, int out_size) {
    const float* tgt = (const float*)d_in[0];
    const float* outp = (const float*)d_in[1];
    float* out = (float*)d_out;

    k_per_image<<<NBATCH, 128>>>(tgt, outp);
    k_scan<<<60, 1024>>>();
    k_ap<<<AP_GRID, 256>>>(out);
}